// round 16
// baseline (speedup 1.0000x reference)
#include <cuda_runtime.h>
#include <cuda_fp16.h>
#include <cstdint>

#define N_NODES 50000
#define EMAX 1600000
#define LDA 144
#define GBLK_TC 391      // ceil(N_NODES/128)

// ---------------- scratch (static __device__, no allocation) ----------------
__device__ float    g_A[N_NODES * LDA];   // layer-1 GEMM input, stride 144
__device__ float    g_h1[N_NODES * 128];  // relu output layer 1
__device__ uint32_t g_ub[N_NODES * 32];   // u = h1@W2_nbr as fp16x2 (64 half/row)
__device__ float    g_ur[N_NODES * 64];   // r = h1@W2_root fp32
__device__ uint32_t g_h2h[N_NODES * 32];  // final embeddings fp16x2 (64 half/row)
__device__ float    g_deginv[N_NODES];
__device__ int      g_deg[N_NODES];
__device__ int      g_cur[N_NODES];       // running cursor, initialized to bucket base
__device__ int      g_rowptr[N_NODES];
__device__ int      g_total;
__device__ int2     g_csre[EMAX];         // (src id, edge id) bucketed by dst
// bf16x2-packed weight k-pairs: [kpair][n], lo half = even k, hi half = odd k
__device__ uint32_t g_W1h2[72 * 128];
__device__ uint32_t g_W1l2[72 * 128];
__device__ uint32_t g_W2h2[64 * 128];
__device__ uint32_t g_W2l2[64 * 128];

// ---------------- bf16 / fp16 helpers ----------------
__device__ __forceinline__ uint32_t bf2_of(float odd, float even) {
    uint32_t r; asm("cvt.rn.bf16x2.f32 %0, %1, %2;" : "=r"(r) : "f"(odd), "f"(even));
    return r;
}
__device__ __forceinline__ void split_pair(float e, float o, uint32_t &hi, uint32_t &lo) {
    hi = bf2_of(o, e);
    float ef = __uint_as_float(hi << 16);
    float of = __uint_as_float(hi & 0xffff0000u);
    lo = bf2_of(o - of, e - ef);
}
__device__ __forceinline__ uint32_t h2_of(float e, float o) {
    __half2 h = __floats2half2_rn(e, o);
    return *reinterpret_cast<uint32_t*>(&h);
}
__device__ __forceinline__ float2 h2f(uint32_t u) {
    __half2 h = *reinterpret_cast<__half2*>(&u);
    return __half22float2(h);
}
__device__ __forceinline__ void mma_bf16(float* c, const uint32_t* a, uint32_t b0, uint32_t b1) {
    asm volatile(
        "mma.sync.aligned.m16n8k16.row.col.f32.bf16.bf16.f32 "
        "{%0,%1,%2,%3}, {%4,%5,%6,%7}, {%8,%9}, {%0,%1,%2,%3};"
        : "+f"(c[0]), "+f"(c[1]), "+f"(c[2]), "+f"(c[3])
        : "r"(a[0]), "r"(a[1]), "r"(a[2]), "r"(a[3]), "r"(b0), "r"(b1));
}

// ---------------- fused prep: zero deg + split weights + build A cols 0..67 ----
__global__ void k_prepw(const float* __restrict__ W1r, const float* __restrict__ W1n,
                        const float* __restrict__ W2r, const float* __restrict__ W2n,
                        const float* __restrict__ x,   const float* __restrict__ pos) {
    int t0 = blockIdx.x * blockDim.x + threadIdx.x;
    int stride = gridDim.x * blockDim.x;
    if (t0 == 0) g_total = 0;
    for (int i = t0; i < N_NODES; i += stride) g_deg[i] = 0;
    for (int i = t0; i < 72 * 128; i += stride) {
        int kp = i >> 7, n = i & 127;
        int r0 = 2 * kp, r1 = 2 * kp + 1;
        float we = 0.f, wo = 0.f;
        if (r0 < 66) we = W1r[r0 * 128 + n];
        else if (r0 >= 68 && r0 < 134) we = W1n[(r0 - 68) * 128 + n];
        if (r1 < 66) wo = W1r[r1 * 128 + n];
        else if (r1 >= 68 && r1 < 134) wo = W1n[(r1 - 68) * 128 + n];
        uint32_t hi, lo;
        split_pair(we, wo, hi, lo);
        g_W1h2[i] = hi; g_W1l2[i] = lo;
    }
    for (int i = t0; i < 64 * 128; i += stride) {
        int kp = i >> 7, n = i & 127;
        int r0 = 2 * kp, r1 = 2 * kp + 1;
        float we = (n < 64) ? W2n[r0 * 64 + n] : W2r[r0 * 64 + (n - 64)];
        float wo = (n < 64) ? W2n[r1 * 64 + n] : W2r[r1 * 64 + (n - 64)];
        uint32_t hi, lo;
        split_pair(we, wo, hi, lo);
        g_W2h2[i] = hi; g_W2l2[i] = lo;
    }
    // A cols 0..67 = concat(x, pos) fp32 (root path, exact)
    for (int i = t0; i < N_NODES * 68; i += stride) {
        int n = i / 68, c = i % 68;
        float v = 0.0f;
        if (c < 64) v = x[n * 64 + c];
        else if (c < 66) v = pos[n * 2 + (c - 64)];
        g_A[(size_t)n * LDA + c] = v;
    }
}

__global__ void k_deg(const int* __restrict__ dst, int E) {
    int i = blockIdx.x * blockDim.x + threadIdx.x;
    if (i < E) atomicAdd(&g_deg[dst[i]], 1);
}

// CSR bucket bases via warp-aggregated atomic on a global cursor (order-free).
__global__ void k_base() {
    int i = blockIdx.x * blockDim.x + threadIdx.x;
    int lane = threadIdx.x & 31;
    int d = (i < N_NODES) ? g_deg[i] : 0;
    int s = d;
    #pragma unroll
    for (int off = 1; off < 32; off <<= 1) {
        int t = __shfl_up_sync(0xffffffffu, s, off);
        if (lane >= off) s += t;
    }
    int base = 0;
    if (lane == 31) base = atomicAdd(&g_total, s);
    base = __shfl_sync(0xffffffffu, base, 31);
    if (i < N_NODES) {
        int b = base + s - d;
        g_rowptr[i] = b;
        g_cur[i]    = b;
        g_deginv[i] = 1.0f / fmaxf((float)d, 1.0f);
    }
}

__global__ void k_fillcsr(const int* __restrict__ src, const int* __restrict__ dst, int E) {
    int e = blockIdx.x * blockDim.x + threadIdx.x;
    if (e >= E) return;
    int d = dst[e];
    int pos = atomicAdd(&g_cur[d], 1);
    g_csre[pos] = make_int2(src[e], e);
}

// ---------------- layer-1 aggregation (fp32, exact) ----------------
__global__ __launch_bounds__(256) void k_agg1(const float* __restrict__ x,
                                              const float* __restrict__ pos) {
    int gt = blockIdx.x * blockDim.x + threadIdx.x;
    int w = gt >> 5, lane = gt & 31;
    if (w >= N_NODES) return;
    int start = g_rowptr[w], end = start + g_deg[w];
    float ax = 0.f, ay = 0.f, px = 0.f, py = 0.f;
    const float2* x2 = (const float2*)x;
    const float2* p2 = (const float2*)pos;
    for (int i = start; i < end; i += 32) {
        int m = min(32, end - i);
        int eid = (i + lane < end) ? g_csre[i + lane].x : 0;
        for (int j = 0; j < m; j++) {
            int s = __shfl_sync(0xffffffffu, eid, j);
            float2 v = __ldg(x2 + (size_t)s * 32 + lane);
            ax += v.x; ay += v.y;
            if (lane == 0) { float2 p = __ldg(p2 + s); px += p.x; py += p.y; }
        }
    }
    float di = g_deginv[w];
    float* rowp = g_A + (size_t)w * LDA;
    rowp[68 + lane * 2]     = ax * di;
    rowp[68 + lane * 2 + 1] = ay * di;
    if (lane == 0) { rowp[132] = px * di; rowp[133] = py * di; }
}

// ---------------- bf16 tensor-core GEMM ----------------
template <int MODE>
__global__ __launch_bounds__(256) void k_gemm_bf(const float* __restrict__ bias) {
    const int KP  = (MODE == 0) ? 72 : 64;
    const int lda = (MODE == 0) ? 144 : 128;
    const float* __restrict__ A = (MODE == 0) ? g_A : g_h1;
    const uint32_t* __restrict__ BH = (MODE == 0) ? g_W1h2 : g_W2h2;
    const uint32_t* __restrict__ BL = (MODE == 0) ? g_W1l2 : g_W2l2;

    __shared__ float    As[16][132];
    __shared__ uint32_t Bsh[8][136];
    __shared__ uint32_t Bsl[8][136];

    int tid  = threadIdx.x;
    int wid  = tid >> 5, lane = tid & 31;
    int tg   = lane & 3, gid = lane >> 2;
    int m0   = blockIdx.x * 128;
    int mrow = wid * 16 + gid;

    int arow = tid >> 1;
    int ak   = (tid & 1) * 8;
    int a_grow = min(m0 + arow, N_NODES - 1);
    int brow = tid >> 5;
    int bcol = (tid & 31) * 4;

    float acc[16][4];
    #pragma unroll
    for (int t = 0; t < 16; t++)
        #pragma unroll
        for (int i = 0; i < 4; i++) acc[t][i] = 0.0f;

    for (int kp0 = 0; kp0 < KP; kp0 += 8) {
        int k0 = kp0 * 2;
        float4 av0 = *(const float4*)(A + (size_t)a_grow * lda + k0 + ak);
        float4 av1 = *(const float4*)(A + (size_t)a_grow * lda + k0 + ak + 4);
        uint4 bh4 = *(const uint4*)(BH + (size_t)(kp0 + brow) * 128 + bcol);
        uint4 bl4 = *(const uint4*)(BL + (size_t)(kp0 + brow) * 128 + bcol);
        __syncthreads();
        As[ak + 0][arow] = av0.x; As[ak + 1][arow] = av0.y;
        As[ak + 2][arow] = av0.z; As[ak + 3][arow] = av0.w;
        As[ak + 4][arow] = av1.x; As[ak + 5][arow] = av1.y;
        As[ak + 6][arow] = av1.z; As[ak + 7][arow] = av1.w;
        *(uint4*)&Bsh[brow][bcol] = bh4;
        *(uint4*)&Bsl[brow][bcol] = bl4;
        __syncthreads();

        float ae0 = As[2 * tg][mrow],     ao0 = As[2 * tg + 1][mrow];
        float ae1 = As[2 * tg][mrow + 8], ao1 = As[2 * tg + 1][mrow + 8];
        float ae2 = As[2 * tg + 8][mrow],     ao2 = As[2 * tg + 9][mrow];
        float ae3 = As[2 * tg + 8][mrow + 8], ao3 = As[2 * tg + 9][mrow + 8];
        uint32_t ah[4], al[4];
        split_pair(ae0, ao0, ah[0], al[0]);
        split_pair(ae1, ao1, ah[1], al[1]);
        split_pair(ae2, ao2, ah[2], al[2]);
        split_pair(ae3, ao3, ah[3], al[3]);

        #pragma unroll
        for (int t = 0; t < 16; t++) {
            int n = t * 8 + gid;
            uint32_t bh0 = Bsh[tg][n], bh1 = Bsh[tg + 4][n];
            uint32_t bl0 = Bsl[tg][n], bl1 = Bsl[tg + 4][n];
            mma_bf16(acc[t], ah, bh0, bh1);
            mma_bf16(acc[t], al, bh0, bh1);
            mma_bf16(acc[t], ah, bl0, bl1);
        }
    }

    int r0 = m0 + wid * 16 + gid;
    int r1 = r0 + 8;
    #pragma unroll
    for (int t = 0; t < 16; t++) {
        int c = t * 8 + tg * 2;
        float v0 = acc[t][0], v1 = acc[t][1], v2 = acc[t][2], v3 = acc[t][3];
        if (MODE == 0) {
            float bb0 = bias[c], bb1 = bias[c + 1];
            v0 = fmaxf(v0 + bb0, 0.f); v1 = fmaxf(v1 + bb1, 0.f);
            v2 = fmaxf(v2 + bb0, 0.f); v3 = fmaxf(v3 + bb1, 0.f);
            if (r0 < N_NODES) *(float2*)&g_h1[(size_t)r0 * 128 + c] = make_float2(v0, v1);
            if (r1 < N_NODES) *(float2*)&g_h1[(size_t)r1 * 128 + c] = make_float2(v2, v3);
        } else {
            if (c < 64) {   // nbr half -> fp16x2 (averaged later; safe)
                if (r0 < N_NODES) g_ub[r0 * 32 + (c >> 1)] = h2_of(v0, v1);
                if (r1 < N_NODES) g_ub[r1 * 32 + (c >> 1)] = h2_of(v2, v3);
            } else {        // root half -> fp32
                if (r0 < N_NODES) *(float2*)&g_ur[(size_t)r0 * 64 + (c - 64)] = make_float2(v0, v1);
                if (r1 < N_NODES) *(float2*)&g_ur[(size_t)r1 * 64 + (c - 64)] = make_float2(v2, v3);
            }
        }
    }
}

// ---------------- layer-2 aggregation over fp16 u rows (+ fused final, fp16 h2) ----
__global__ __launch_bounds__(256) void k_agg2(const float* __restrict__ b2) {
    int gt = blockIdx.x * blockDim.x + threadIdx.x;
    int w = gt >> 5, lane = gt & 31;
    if (w >= N_NODES) return;
    int start = g_rowptr[w], end = start + g_deg[w];
    float ax = 0.f, ay = 0.f;
    for (int i = start; i < end; i += 32) {
        int m = min(32, end - i);
        int eid = (i + lane < end) ? g_csre[i + lane].x : 0;
        for (int j = 0; j < m; j++) {
            int s = __shfl_sync(0xffffffffu, eid, j);
            float2 v = h2f(__ldg(g_ub + (size_t)s * 32 + lane));
            ax += v.x; ay += v.y;
        }
    }
    float di = g_deginv[w];
    float rx = g_ur[(size_t)w * 64 + lane * 2];
    float ry = g_ur[(size_t)w * 64 + lane * 2 + 1];
    float o0 = rx + ax * di + b2[lane * 2];
    float o1 = ry + ay * di + b2[lane * 2 + 1];
    g_h2h[w * 32 + lane] = h2_of(o0, o1);
}

// ---------------- edge dot over fp16 h2: warp/dst, 8 lanes/edge, 4 edges/iter ----
__global__ __launch_bounds__(256) void k_edge3(float* __restrict__ out) {
    int gt = blockIdx.x * blockDim.x + threadIdx.x;
    int w = gt >> 5, lane = gt & 31;
    if (w >= N_NODES) return;
    int g = lane >> 3;
    int k = lane & 7;
    const uint4* h4 = (const uint4*)g_h2h;   // row = 8 uint4 (64 half)
    uint4 dd = h4[(size_t)w * 8 + k];
    float2 d0 = h2f(dd.x), d1 = h2f(dd.y), d2 = h2f(dd.z), d3 = h2f(dd.w);
    int start = g_rowptr[w], end = start + g_deg[w];
    for (int i = start; i < end; i += 4) {
        int idx = i + g;
        bool valid = idx < end;
        int s = 0, eid = 0;
        if (valid) { int2 ce = g_csre[idx]; s = ce.x; eid = ce.y; }
        float acc = 0.f;
        if (valid) {
            uint4 aa = __ldg(&h4[(size_t)s * 8 + k]);
            float2 a0 = h2f(aa.x), a1 = h2f(aa.y), a2 = h2f(aa.z), a3 = h2f(aa.w);
            acc = a0.x * d0.x + a0.y * d0.y + a1.x * d1.x + a1.y * d1.y
                + a2.x * d2.x + a2.y * d2.y + a3.x * d3.x + a3.y * d3.y;
        }
        acc += __shfl_xor_sync(0xffffffffu, acc, 1);
        acc += __shfl_xor_sync(0xffffffffu, acc, 2);
        acc += __shfl_xor_sync(0xffffffffu, acc, 4);
        if (valid && k == 0) out[eid] = acc;
    }
}

// ---------------- launch ----------------
extern "C" void kernel_launch(void* const* d_in, const int* in_sizes, int n_in,
                              void* d_out, int out_size) {
    const float* x   = (const float*)d_in[0];
    const float* pos = (const float*)d_in[1];
    const int*   ei  = (const int*)d_in[2];
    const float* W1r = (const float*)d_in[3];
    const float* W1n = (const float*)d_in[4];
    const float* b1  = (const float*)d_in[5];
    const float* W2r = (const float*)d_in[6];
    const float* W2n = (const float*)d_in[7];
    const float* b2  = (const float*)d_in[8];
    float* out = (float*)d_out;

    int E = in_sizes[2] / 2;
    const int* src = ei;
    const int* dst = ei + E;

    k_prepw<<<160, 256>>>(W1r, W1n, W2r, W2n, x, pos);
    k_deg<<<(E + 255) / 256, 256>>>(dst, E);
    k_base<<<(N_NODES + 255) / 256, 256>>>();
    k_fillcsr<<<(E + 255) / 256, 256>>>(src, dst, E);
    k_agg1<<<(N_NODES * 32 + 255) / 256, 256>>>(x, pos);
    k_gemm_bf<0><<<GBLK_TC, 256>>>(b1);
    k_gemm_bf<1><<<GBLK_TC, 256>>>(b1);
    k_agg2<<<(N_NODES * 32 + 255) / 256, 256>>>(b2);
    k_edge3<<<(N_NODES * 32 + 255) / 256, 256>>>(out);
}

// round 17
// speedup vs baseline: 1.3530x; 1.3530x over previous
#include <cuda_runtime.h>
#include <cuda_fp16.h>
#include <cstdint>

#define N_NODES 50000
#define EMAX 1600000
#define LDA 144
#define GBLK_TC 391      // ceil(N_NODES/128)

// ---------------- scratch (static __device__, no allocation) ----------------
__device__ float    g_A[N_NODES * LDA];   // layer-1 GEMM input, stride 144
__device__ float    g_h1[N_NODES * 128];  // relu output layer 1
__device__ uint32_t g_ub[N_NODES * 32];   // u = h1@W2_nbr as fp16x2 (64 half/row)
__device__ float    g_ur[N_NODES * 64];   // r = h1@W2_root fp32
__device__ uint32_t g_h2h[N_NODES * 32];  // final embeddings fp16x2 (64 half/row)
__device__ float    g_deginv[N_NODES];
__device__ int      g_deg[N_NODES];
__device__ int      g_cur[N_NODES];       // running cursor, initialized to bucket base
__device__ int      g_rowptr[N_NODES];
__device__ int      g_total;
__device__ int2     g_csre[EMAX];         // (src id, edge id) bucketed by dst
// bf16x2-packed weight k-pairs: [kpair][n], lo half = even k, hi half = odd k
__device__ uint32_t g_W1h2[72 * 128];
__device__ uint32_t g_W1l2[72 * 128];
__device__ uint32_t g_W2h2[64 * 128];
__device__ uint32_t g_W2l2[64 * 128];

// ---------------- bf16 / fp16 helpers ----------------
__device__ __forceinline__ uint32_t bf2_of(float odd, float even) {
    uint32_t r; asm("cvt.rn.bf16x2.f32 %0, %1, %2;" : "=r"(r) : "f"(odd), "f"(even));
    return r;
}
__device__ __forceinline__ void split_pair(float e, float o, uint32_t &hi, uint32_t &lo) {
    hi = bf2_of(o, e);
    float ef = __uint_as_float(hi << 16);
    float of = __uint_as_float(hi & 0xffff0000u);
    lo = bf2_of(o - of, e - ef);
}
__device__ __forceinline__ uint32_t h2_of(float e, float o) {
    __half2 h = __floats2half2_rn(e, o);
    return *reinterpret_cast<uint32_t*>(&h);
}
// fp16 -> fp32 via ALU bit ops (exact for normals; zeros/subnormals err <= 6e-5 abs)
__device__ __forceinline__ float2 h2f_fast(uint32_t u) {
    uint32_t lo = u & 0xffffu, hi = u >> 16;
    uint32_t flo = ((lo & 0x8000u) << 16) | (((lo & 0x7fffu) << 13) + 0x38000000u);
    uint32_t fhi = ((hi & 0x8000u) << 16) | (((hi & 0x7fffu) << 13) + 0x38000000u);
    float2 r;
    r.x = __uint_as_float(flo);
    r.y = __uint_as_float(fhi);
    return r;
}
__device__ __forceinline__ void mma_bf16(float* c, const uint32_t* a, uint32_t b0, uint32_t b1) {
    asm volatile(
        "mma.sync.aligned.m16n8k16.row.col.f32.bf16.bf16.f32 "
        "{%0,%1,%2,%3}, {%4,%5,%6,%7}, {%8,%9}, {%0,%1,%2,%3};"
        : "+f"(c[0]), "+f"(c[1]), "+f"(c[2]), "+f"(c[3])
        : "r"(a[0]), "r"(a[1]), "r"(a[2]), "r"(a[3]), "r"(b0), "r"(b1));
}

// ---------------- fused prep: zero deg + split weights + build A cols 0..67 ----
__global__ void k_prepw(const float* __restrict__ W1r, const float* __restrict__ W1n,
                        const float* __restrict__ W2r, const float* __restrict__ W2n,
                        const float* __restrict__ x,   const float* __restrict__ pos) {
    int t0 = blockIdx.x * blockDim.x + threadIdx.x;
    int stride = gridDim.x * blockDim.x;
    if (t0 == 0) g_total = 0;
    for (int i = t0; i < N_NODES; i += stride) g_deg[i] = 0;
    for (int i = t0; i < 72 * 128; i += stride) {
        int kp = i >> 7, n = i & 127;
        int r0 = 2 * kp, r1 = 2 * kp + 1;
        float we = 0.f, wo = 0.f;
        if (r0 < 66) we = W1r[r0 * 128 + n];
        else if (r0 >= 68 && r0 < 134) we = W1n[(r0 - 68) * 128 + n];
        if (r1 < 66) wo = W1r[r1 * 128 + n];
        else if (r1 >= 68 && r1 < 134) wo = W1n[(r1 - 68) * 128 + n];
        uint32_t hi, lo;
        split_pair(we, wo, hi, lo);
        g_W1h2[i] = hi; g_W1l2[i] = lo;
    }
    for (int i = t0; i < 64 * 128; i += stride) {
        int kp = i >> 7, n = i & 127;
        int r0 = 2 * kp, r1 = 2 * kp + 1;
        float we = (n < 64) ? W2n[r0 * 64 + n] : W2r[r0 * 64 + (n - 64)];
        float wo = (n < 64) ? W2n[r1 * 64 + n] : W2r[r1 * 64 + (n - 64)];
        uint32_t hi, lo;
        split_pair(we, wo, hi, lo);
        g_W2h2[i] = hi; g_W2l2[i] = lo;
    }
    for (int i = t0; i < N_NODES * 68; i += stride) {
        int n = i / 68, c = i % 68;
        float v = 0.0f;
        if (c < 64) v = x[n * 64 + c];
        else if (c < 66) v = pos[n * 2 + (c - 64)];
        g_A[(size_t)n * LDA + c] = v;
    }
}

// 4 edges per thread for atomic-latency ILP
__global__ void k_deg(const int* __restrict__ dst, int E) {
    int t = blockIdx.x * blockDim.x + threadIdx.x;
    int T = gridDim.x * blockDim.x;
    int e0 = t, e1 = t + T, e2 = t + 2 * T, e3 = t + 3 * T;
    int d0 = 0, d1 = 0, d2 = 0, d3 = 0;
    if (e0 < E) d0 = dst[e0];
    if (e1 < E) d1 = dst[e1];
    if (e2 < E) d2 = dst[e2];
    if (e3 < E) d3 = dst[e3];
    if (e0 < E) atomicAdd(&g_deg[d0], 1);
    if (e1 < E) atomicAdd(&g_deg[d1], 1);
    if (e2 < E) atomicAdd(&g_deg[d2], 1);
    if (e3 < E) atomicAdd(&g_deg[d3], 1);
}

// CSR bucket bases via warp-aggregated atomic on a global cursor (order-free).
__global__ void k_base() {
    int i = blockIdx.x * blockDim.x + threadIdx.x;
    int lane = threadIdx.x & 31;
    int d = (i < N_NODES) ? g_deg[i] : 0;
    int s = d;
    #pragma unroll
    for (int off = 1; off < 32; off <<= 1) {
        int t = __shfl_up_sync(0xffffffffu, s, off);
        if (lane >= off) s += t;
    }
    int base = 0;
    if (lane == 31) base = atomicAdd(&g_total, s);
    base = __shfl_sync(0xffffffffu, base, 31);
    if (i < N_NODES) {
        int b = base + s - d;
        g_rowptr[i] = b;
        g_cur[i]    = b;
        g_deginv[i] = 1.0f / fmaxf((float)d, 1.0f);
    }
}

// 4 edges per thread for atomic-latency ILP
__global__ void k_fillcsr(const int* __restrict__ src, const int* __restrict__ dst, int E) {
    int t = blockIdx.x * blockDim.x + threadIdx.x;
    int T = gridDim.x * blockDim.x;
    int e0 = t, e1 = t + T, e2 = t + 2 * T, e3 = t + 3 * T;
    int s0 = 0, s1 = 0, s2 = 0, s3 = 0, d0 = 0, d1 = 0, d2 = 0, d3 = 0;
    if (e0 < E) { s0 = src[e0]; d0 = dst[e0]; }
    if (e1 < E) { s1 = src[e1]; d1 = dst[e1]; }
    if (e2 < E) { s2 = src[e2]; d2 = dst[e2]; }
    if (e3 < E) { s3 = src[e3]; d3 = dst[e3]; }
    int p0 = 0, p1 = 0, p2 = 0, p3 = 0;
    if (e0 < E) p0 = atomicAdd(&g_cur[d0], 1);
    if (e1 < E) p1 = atomicAdd(&g_cur[d1], 1);
    if (e2 < E) p2 = atomicAdd(&g_cur[d2], 1);
    if (e3 < E) p3 = atomicAdd(&g_cur[d3], 1);
    if (e0 < E) g_csre[p0] = make_int2(s0, e0);
    if (e1 < E) g_csre[p1] = make_int2(s1, e1);
    if (e2 < E) g_csre[p2] = make_int2(s2, e2);
    if (e3 < E) g_csre[p3] = make_int2(s3, e3);
}

// ---------------- layer-1 aggregation (fp32, exact) ----------------
__global__ __launch_bounds__(256) void k_agg1(const float* __restrict__ x,
                                              const float* __restrict__ pos) {
    int gt = blockIdx.x * blockDim.x + threadIdx.x;
    int w = gt >> 5, lane = gt & 31;
    if (w >= N_NODES) return;
    int start = g_rowptr[w], end = start + g_deg[w];
    float ax = 0.f, ay = 0.f, px = 0.f, py = 0.f;
    const float2* x2 = (const float2*)x;
    const float2* p2 = (const float2*)pos;
    for (int i = start; i < end; i += 32) {
        int m = min(32, end - i);
        int eid = (i + lane < end) ? g_csre[i + lane].x : 0;
        for (int j = 0; j < m; j++) {
            int s = __shfl_sync(0xffffffffu, eid, j);
            float2 v = __ldg(x2 + (size_t)s * 32 + lane);
            ax += v.x; ay += v.y;
            if (lane == 0) { float2 p = __ldg(p2 + s); px += p.x; py += p.y; }
        }
    }
    float di = g_deginv[w];
    float* rowp = g_A + (size_t)w * LDA;
    rowp[68 + lane * 2]     = ax * di;
    rowp[68 + lane * 2 + 1] = ay * di;
    if (lane == 0) { rowp[132] = px * di; rowp[133] = py * di; }
}

// ---------------- bf16 tensor-core GEMM ----------------
template <int MODE>
__global__ __launch_bounds__(256) void k_gemm_bf(const float* __restrict__ bias) {
    const int KP  = (MODE == 0) ? 72 : 64;
    const int lda = (MODE == 0) ? 144 : 128;
    const float* __restrict__ A = (MODE == 0) ? g_A : g_h1;
    const uint32_t* __restrict__ BH = (MODE == 0) ? g_W1h2 : g_W2h2;
    const uint32_t* __restrict__ BL = (MODE == 0) ? g_W1l2 : g_W2l2;

    __shared__ float    As[16][132];
    __shared__ uint32_t Bsh[8][136];
    __shared__ uint32_t Bsl[8][136];

    int tid  = threadIdx.x;
    int wid  = tid >> 5, lane = tid & 31;
    int tg   = lane & 3, gid = lane >> 2;
    int m0   = blockIdx.x * 128;
    int mrow = wid * 16 + gid;

    int arow = tid >> 1;
    int ak   = (tid & 1) * 8;
    int a_grow = min(m0 + arow, N_NODES - 1);
    int brow = tid >> 5;
    int bcol = (tid & 31) * 4;

    float acc[16][4];
    #pragma unroll
    for (int t = 0; t < 16; t++)
        #pragma unroll
        for (int i = 0; i < 4; i++) acc[t][i] = 0.0f;

    for (int kp0 = 0; kp0 < KP; kp0 += 8) {
        int k0 = kp0 * 2;
        float4 av0 = *(const float4*)(A + (size_t)a_grow * lda + k0 + ak);
        float4 av1 = *(const float4*)(A + (size_t)a_grow * lda + k0 + ak + 4);
        uint4 bh4 = *(const uint4*)(BH + (size_t)(kp0 + brow) * 128 + bcol);
        uint4 bl4 = *(const uint4*)(BL + (size_t)(kp0 + brow) * 128 + bcol);
        __syncthreads();
        As[ak + 0][arow] = av0.x; As[ak + 1][arow] = av0.y;
        As[ak + 2][arow] = av0.z; As[ak + 3][arow] = av0.w;
        As[ak + 4][arow] = av1.x; As[ak + 5][arow] = av1.y;
        As[ak + 6][arow] = av1.z; As[ak + 7][arow] = av1.w;
        *(uint4*)&Bsh[brow][bcol] = bh4;
        *(uint4*)&Bsl[brow][bcol] = bl4;
        __syncthreads();

        float ae0 = As[2 * tg][mrow],     ao0 = As[2 * tg + 1][mrow];
        float ae1 = As[2 * tg][mrow + 8], ao1 = As[2 * tg + 1][mrow + 8];
        float ae2 = As[2 * tg + 8][mrow],     ao2 = As[2 * tg + 9][mrow];
        float ae3 = As[2 * tg + 8][mrow + 8], ao3 = As[2 * tg + 9][mrow + 8];
        uint32_t ah[4], al[4];
        split_pair(ae0, ao0, ah[0], al[0]);
        split_pair(ae1, ao1, ah[1], al[1]);
        split_pair(ae2, ao2, ah[2], al[2]);
        split_pair(ae3, ao3, ah[3], al[3]);

        #pragma unroll
        for (int t = 0; t < 16; t++) {
            int n = t * 8 + gid;
            uint32_t bh0 = Bsh[tg][n], bh1 = Bsh[tg + 4][n];
            uint32_t bl0 = Bsl[tg][n], bl1 = Bsl[tg + 4][n];
            mma_bf16(acc[t], ah, bh0, bh1);
            mma_bf16(acc[t], al, bh0, bh1);
            mma_bf16(acc[t], ah, bl0, bl1);
        }
    }

    int r0 = m0 + wid * 16 + gid;
    int r1 = r0 + 8;
    #pragma unroll
    for (int t = 0; t < 16; t++) {
        int c = t * 8 + tg * 2;
        float v0 = acc[t][0], v1 = acc[t][1], v2 = acc[t][2], v3 = acc[t][3];
        if (MODE == 0) {
            float bb0 = bias[c], bb1 = bias[c + 1];
            v0 = fmaxf(v0 + bb0, 0.f); v1 = fmaxf(v1 + bb1, 0.f);
            v2 = fmaxf(v2 + bb0, 0.f); v3 = fmaxf(v3 + bb1, 0.f);
            if (r0 < N_NODES) *(float2*)&g_h1[(size_t)r0 * 128 + c] = make_float2(v0, v1);
            if (r1 < N_NODES) *(float2*)&g_h1[(size_t)r1 * 128 + c] = make_float2(v2, v3);
        } else {
            if (c < 64) {   // nbr half -> fp16x2 (averaged later; safe)
                if (r0 < N_NODES) g_ub[r0 * 32 + (c >> 1)] = h2_of(v0, v1);
                if (r1 < N_NODES) g_ub[r1 * 32 + (c >> 1)] = h2_of(v2, v3);
            } else {        // root half -> fp32
                if (r0 < N_NODES) *(float2*)&g_ur[(size_t)r0 * 64 + (c - 64)] = make_float2(v0, v1);
                if (r1 < N_NODES) *(float2*)&g_ur[(size_t)r1 * 64 + (c - 64)] = make_float2(v2, v3);
            }
        }
    }
}

// ---------------- layer-2 aggregation over fp16 u rows (+ fused final, fp16 h2) ----
__global__ __launch_bounds__(256) void k_agg2(const float* __restrict__ b2) {
    int gt = blockIdx.x * blockDim.x + threadIdx.x;
    int w = gt >> 5, lane = gt & 31;
    if (w >= N_NODES) return;
    int start = g_rowptr[w], end = start + g_deg[w];
    float ax = 0.f, ay = 0.f;
    for (int i = start; i < end; i += 32) {
        int m = min(32, end - i);
        int eid = (i + lane < end) ? g_csre[i + lane].x : 0;
        for (int j = 0; j < m; j++) {
            int s = __shfl_sync(0xffffffffu, eid, j);
            float2 v = h2f_fast(__ldg(g_ub + (size_t)s * 32 + lane));
            ax += v.x; ay += v.y;
        }
    }
    float di = g_deginv[w];
    float rx = g_ur[(size_t)w * 64 + lane * 2];
    float ry = g_ur[(size_t)w * 64 + lane * 2 + 1];
    float o0 = rx + ax * di + b2[lane * 2];
    float o1 = ry + ay * di + b2[lane * 2 + 1];
    g_h2h[w * 32 + lane] = h2_of(o0, o1);
}

// ---------------- edge dot over fp16 h2: warp/dst, 8 lanes/edge, 4 edges/iter ----
__global__ __launch_bounds__(256) void k_edge3(float* __restrict__ out) {
    int gt = blockIdx.x * blockDim.x + threadIdx.x;
    int w = gt >> 5, lane = gt & 31;
    if (w >= N_NODES) return;
    int g = lane >> 3;
    int k = lane & 7;
    const uint4* h4 = (const uint4*)g_h2h;   // row = 8 uint4 (64 half)
    uint4 dd = h4[(size_t)w * 8 + k];
    float2 d0 = h2f_fast(dd.x), d1 = h2f_fast(dd.y);
    float2 d2 = h2f_fast(dd.z), d3 = h2f_fast(dd.w);
    int start = g_rowptr[w], end = start + g_deg[w];
    for (int i = start; i < end; i += 4) {
        int idx = i + g;
        bool valid = idx < end;
        int s = 0, eid = 0;
        if (valid) { int2 ce = g_csre[idx]; s = ce.x; eid = ce.y; }
        float acc = 0.f;
        if (valid) {
            uint4 aa = __ldg(&h4[(size_t)s * 8 + k]);
            float2 a0 = h2f_fast(aa.x), a1 = h2f_fast(aa.y);
            float2 a2 = h2f_fast(aa.z), a3 = h2f_fast(aa.w);
            acc = a0.x * d0.x + a0.y * d0.y + a1.x * d1.x + a1.y * d1.y
                + a2.x * d2.x + a2.y * d2.y + a3.x * d3.x + a3.y * d3.y;
        }
        acc += __shfl_xor_sync(0xffffffffu, acc, 1);
        acc += __shfl_xor_sync(0xffffffffu, acc, 2);
        acc += __shfl_xor_sync(0xffffffffu, acc, 4);
        if (valid && k == 0) out[eid] = acc;
    }
}

// ---------------- launch ----------------
extern "C" void kernel_launch(void* const* d_in, const int* in_sizes, int n_in,
                              void* d_out, int out_size) {
    const float* x   = (const float*)d_in[0];
    const float* pos = (const float*)d_in[1];
    const int*   ei  = (const int*)d_in[2];
    const float* W1r = (const float*)d_in[3];
    const float* W1n = (const float*)d_in[4];
    const float* b1  = (const float*)d_in[5];
    const float* W2r = (const float*)d_in[6];
    const float* W2n = (const float*)d_in[7];
    const float* b2  = (const float*)d_in[8];
    float* out = (float*)d_out;

    int E = in_sizes[2] / 2;
    const int* src = ei;
    const int* dst = ei + E;
    int quarter = (E + 3) / 4;

    k_prepw<<<256, 256>>>(W1r, W1n, W2r, W2n, x, pos);
    k_deg<<<(quarter + 255) / 256, 256>>>(dst, E);
    k_base<<<(N_NODES + 255) / 256, 256>>>();
    k_fillcsr<<<(quarter + 255) / 256, 256>>>(src, dst, E);
    k_agg1<<<(N_NODES * 32 + 255) / 256, 256>>>(x, pos);
    k_gemm_bf<0><<<GBLK_TC, 256>>>(b1);
    k_gemm_bf<1><<<GBLK_TC, 256>>>(b1);
    k_agg2<<<(N_NODES * 32 + 255) / 256, 256>>>(b2);
    k_edge3<<<(N_NODES * 32 + 255) / 256, 256>>>(out);
}